// round 15
// baseline (speedup 1.0000x reference)
#include <cuda_runtime.h>
#include <cuda_fp16.h>
#include <cstdint>

// ---------------- problem constants ----------------
#define MDIM 8192
#define NDIM 4096
#define KDIM 4096

// ---------------- GEMM tiling (round-10 proven optimum) ----------------
// CTA tile 128x128, 8 warps (2m x 4n), warp tile 64x32, 2 CTAs per SM.
// KC=64, 3-stage mbarrier async pipeline (no mainloop __syncthreads).
#define MT 128
#define NT 128
#define KC 64                        // halfs per K-chunk = 128 bytes
#define KITERS (KDIM / KC)           // 64
#define NSTAGE 3
#define SROW_B 144                   // smem row stride bytes: 128 data + 16 pad
#define A_WORDS (MT * 36)            // 4608 words
#define B_WORDS (NT * 36)            // 4608 words
#define STAGE_WORDS (A_WORDS + B_WORDS)          // 9216 words = 36864 B
#define STAGE_BYTES (STAGE_WORDS * 4)
#define SMEM_WORDS (NSTAGE * STAGE_WORDS)        // 27648 words
#define SMEM_TOTAL (SMEM_WORDS * 4 + 1024)       // 111616 B (x2 CTAs = 223 KB)

// dequant dynamic smem layout (floats)
#define DQ_DUP_F   (256 * 32)                    // 8192: codebook x32 copies
#define DQ_UST_F   (32 * 64)                     // 2048
#define DQ_VTS_F   (32 * 68)                     // 2176
#define DQ_SMEM_B  ((DQ_DUP_F + DQ_UST_F + DQ_VTS_F) * 4)   // 49664 B

// ---------------- device scratch (static: no allocation) ----------------
__device__ __half g_Wh[(size_t)NDIM * KDIM];     // 32 MB fp16 W (dequant target)
__device__ __half g_xh[(size_t)MDIM * KDIM];     // 64 MB fp16 x

// ---------------- helpers ----------------
__device__ __forceinline__ uint32_t smem_u32(const void* p) {
    uint32_t a;
    asm("{ .reg .u64 t; cvta.to.shared.u64 t, %1; cvt.u32.u64 %0, t; }" : "=r"(a) : "l"(p));
    return a;
}
__device__ __forceinline__ void cp16(uint32_t dst, const void* src) {
    asm volatile("cp.async.cg.shared.global [%0], [%1], 16;" :: "r"(dst), "l"(src));
}
__device__ __forceinline__ void mbar_init(uint32_t a, uint32_t cnt) {
    asm volatile("mbarrier.init.shared.b64 [%0], %1;" :: "r"(a), "r"(cnt) : "memory");
}
__device__ __forceinline__ void mbar_arrive(uint32_t a) {
    asm volatile("mbarrier.arrive.shared.b64 _, [%0];" :: "r"(a) : "memory");
}
__device__ __forceinline__ void cp_arrive_noinc(uint32_t a) {
    asm volatile("cp.async.mbarrier.arrive.noinc.shared.b64 [%0];" :: "r"(a) : "memory");
}
__device__ __forceinline__ void mbar_wait(uint32_t a, uint32_t parity) {
    uint32_t done;
    asm volatile("{\n\t.reg .pred p;\n\t"
                 "mbarrier.try_wait.parity.acquire.cta.shared::cta.b64 p, [%1], %2;\n\t"
                 "selp.b32 %0, 1, 0, p;\n\t}"
                 : "=r"(done) : "r"(a), "r"(parity) : "memory");
    if (!done) {
        asm volatile("{\n\t.reg .pred P1;\n\t"
                     "WLOOP_%=:\n\t"
                     "mbarrier.try_wait.parity.acquire.cta.shared::cta.b64 P1, [%0], %1, 0x989680;\n\t"
                     "@P1 bra.uni WDONE_%=;\n\t"
                     "bra.uni WLOOP_%=;\n\t"
                     "WDONE_%=:\n\t}"
                     :: "r"(a), "r"(parity) : "memory");
    }
}
__device__ __forceinline__ void ldsm4(uint32_t* r, uint32_t addr) {
    asm volatile("ldmatrix.sync.aligned.m8n8.x4.shared.b16 {%0,%1,%2,%3}, [%4];"
        : "=r"(r[0]), "=r"(r[1]), "=r"(r[2]), "=r"(r[3]) : "r"(addr));
}
// mma.sync m16n8k16 fp16 -> fp32 accum
__device__ __forceinline__ void mma_f16(float* d, const uint32_t* a, const uint32_t* b) {
    asm volatile(
        "mma.sync.aligned.m16n8k16.row.col.f32.f16.f16.f32 "
        "{%0,%1,%2,%3}, {%4,%5,%6,%7}, {%8,%9}, {%0,%1,%2,%3};"
        : "+f"(d[0]), "+f"(d[1]), "+f"(d[2]), "+f"(d[3])
        : "r"(a[0]), "r"(a[1]), "r"(a[2]), "r"(a[3]), "r"(b[0]), "r"(b[1]));
}

// ============================================================
// Kernel 1: dequant W -> g_Wh. Tile 64(out) x 64(in), 4x4/thread.
// Codebook duplicated x32 in smem: dup[e*32 + lane] -> bank == lane
// -> conflict-free random gathers.
// ============================================================
__global__ __launch_bounds__(256)
void dequant_kernel(const float* __restrict__ codebook,
                    const int*   __restrict__ indices,
                    const float* __restrict__ U,
                    const float* __restrict__ s,
                    const float* __restrict__ Vt)
{
    extern __shared__ float dsm[];
    float* dup = dsm;                         // [256][32] lane-striped
    float (*UsT)[64] = (float(*)[64])(dsm + DQ_DUP_F);
    float (*Vts)[68] = (float(*)[68])(dsm + DQ_DUP_F + DQ_UST_F);

    const int tid  = threadIdx.x;
    const int lane = tid & 31;
    const int warp = tid >> 5;                // 8 warps
    const int o_base = blockIdx.y * 64;
    const int i_base = blockIdx.x * 64;

    // duplicate codebook: warp w handles entries e = i*8 + w; lane -> its copy
    #pragma unroll
    for (int i = 0; i < 32; i++) {
        int e = i * 8 + warp;
        dup[e * 32 + lane] = codebook[e];
    }
    #pragma unroll
    for (int q = 0; q < 8; q++) {
        int e = tid + 256 * q;
        int o = e >> 5, r = e & 31;
        UsT[r][o] = U[(size_t)(o_base + o) * 32 + r] * s[r];
        int r2 = e >> 6, i = e & 63;
        Vts[r2][i] = Vt[(size_t)r2 * KDIM + i_base + i];
    }
    __syncthreads();

    const int tx = tid & 15, ty = tid >> 4;
    float acc[4][4] = {};
    #pragma unroll
    for (int r = 0; r < 32; r++) {
        float4 a4 = *(const float4*)&UsT[r][ty * 4];
        float4 b4 = *(const float4*)&Vts[r][tx * 4];
        float av[4] = {a4.x, a4.y, a4.z, a4.w};
        float bv[4] = {b4.x, b4.y, b4.z, b4.w};
        #pragma unroll
        for (int io = 0; io < 4; io++)
            #pragma unroll
            for (int ii = 0; ii < 4; ii++)
                acc[io][ii] += av[io] * bv[ii];
    }

    #pragma unroll
    for (int io = 0; io < 4; io++) {
        int row = o_base + ty * 4 + io;
        size_t off = (size_t)row * KDIM + i_base + tx * 4;
        const int4 id4 = *(const int4*)&indices[off];
        __half2 h0 = __floats2half2_rn(dup[id4.x * 32 + lane] + acc[io][0],
                                       dup[id4.y * 32 + lane] + acc[io][1]);
        __half2 h1 = __floats2half2_rn(dup[id4.z * 32 + lane] + acc[io][2],
                                       dup[id4.w * 32 + lane] + acc[io][3]);
        uint2 o2;
        o2.x = *reinterpret_cast<uint32_t*>(&h0);
        o2.y = *reinterpret_cast<uint32_t*>(&h1);
        *(uint2*)&g_Wh[off] = o2;
    }
}

// ============================================================
// Kernel 2: x fp32 -> fp16 (8 elems/thread) — low regs, high occ
// ============================================================
__global__ __launch_bounds__(256)
void cvt_x_kernel(const float* __restrict__ x)
{
    size_t i = ((size_t)blockIdx.x * 256 + threadIdx.x) * 8;
    float4 f0 = *(const float4*)&x[i];
    float4 f1 = *(const float4*)&x[i + 4];
    __half2 h0 = __floats2half2_rn(f0.x, f0.y);
    __half2 h1 = __floats2half2_rn(f0.z, f0.w);
    __half2 h2 = __floats2half2_rn(f1.x, f1.y);
    __half2 h3 = __floats2half2_rn(f1.z, f1.w);
    uint4 o;
    o.x = *reinterpret_cast<uint32_t*>(&h0);
    o.y = *reinterpret_cast<uint32_t*>(&h1);
    o.z = *reinterpret_cast<uint32_t*>(&h2);
    o.w = *reinterpret_cast<uint32_t*>(&h3);
    *(uint4*)&g_xh[i] = o;
}

// ============================================================
// Kernel 3: sparse sidecar scatter (fp16 atomics into g_Wh)
// ============================================================
__global__ void scatter_kernel(const int* __restrict__ rows,
                               const int* __restrict__ cols,
                               const float* __restrict__ deltas, int n)
{
    int i = blockIdx.x * blockDim.x + threadIdx.x;
    if (i < n)
        atomicAdd(&g_Wh[(size_t)rows[i] * KDIM + cols[i]],
                  __float2half(deltas[i]));
}

// ============================================================
// Kernel 4: out = x @ W^T + bias   (round-10 GEMM, verbatim)
// CTA 128x128, 256 thr (8 warps, 2m x 4n), warp tile 64x32,
// 3-stage mbarrier async pipeline, 2 CTAs per SM.
// ============================================================
__global__ __launch_bounds__(256, 2)
void gemm_kernel(const float* __restrict__ bias, float* __restrict__ out)
{
    extern __shared__ uint32_t smem[];
    float* bias_s = (float*)(smem + SMEM_WORDS);

    const int tid  = threadIdx.x;
    const int wid  = tid >> 5, lane = tid & 31;
    const int g    = lane >> 2, c = lane & 3;          // quad group / id
    const int warp_m = wid & 1, warp_n = wid >> 1;
    const int m_off  = warp_m * 64, n_off = warp_n * 32;
    const int m_base = blockIdx.y * MT;
    const int n_base = blockIdx.x * NT;

    const uint32_t sbase   = smem_u32(smem);
    const uint32_t mb_full = sbase + SMEM_WORDS * 4 + 512;   // 3 x 8 B
    const uint32_t mb_emp  = mb_full + 24;                   // 3 x 8 B

    if (tid < NT) bias_s[tid] = bias[n_base + tid];
    if (tid == 0) {
        #pragma unroll
        for (int st = 0; st < NSTAGE; st++) {
            mbar_init(mb_full + st * 8, 256);   // one cp-arrive per thread
            mbar_init(mb_emp  + st * 8, 8);     // one arrive per warp
        }
    }
    __syncthreads();                            // barriers visible; only sync

    const __half* xrow = g_xh + (size_t)m_base * KDIM;
    const __half* wrow = g_Wh + (size_t)n_base * KDIM;

    // ldmatrix per-lane byte offsets (within a stage)
    const uint32_t a_lm = (uint32_t)(m_off + ((lane >> 3) & 1) * 8 + (lane & 7)) * SROW_B
                        + (lane >> 4) * 16;
    const uint32_t b_lm = (uint32_t)(n_off + (lane >> 4) * 8 + (lane & 7)) * SROW_B
                        + ((lane >> 3) & 1) * 16;

    // producer: wait stage-empty, fill via cp.async, arm full barrier
    auto produce = [&](int j) {
        int st = j % NSTAGE;
        mbar_wait(mb_emp + st * 8, ((j / NSTAGE) & 1) ^ 1);
        uint32_t a0 = sbase + (uint32_t)st * STAGE_BYTES;
        uint32_t b0 = a0 + A_WORDS * 4;
        const __half* as = xrow + (size_t)j * KC;
        const __half* bs = wrow + (size_t)j * KC;
        #pragma unroll
        for (int q = 0; q < 4; q++) {                  // A: 1024 segs / 256 thr
            int e = tid + 256 * q;
            int row = e >> 3, seg = e & 7;
            cp16(a0 + row * SROW_B + seg * 16, as + (size_t)row * KDIM + seg * 8);
        }
        #pragma unroll
        for (int q = 0; q < 4; q++) {                  // B: 1024 segs / 256 thr
            int e = tid + 256 * q;
            int row = e >> 3, seg = e & 7;
            cp16(b0 + row * SROW_B + seg * 16, bs + (size_t)row * KDIM + seg * 8);
        }
        cp_arrive_noinc(mb_full + st * 8);
    };

    produce(0);
    produce(1);

    float acc[4][4][4] = {};

    for (int kt = 0; kt < KITERS; kt++) {
        int nxt = kt + NSTAGE - 1;
        if (nxt < KITERS) produce(nxt);

        int st = kt % NSTAGE;
        mbar_wait(mb_full + st * 8, (kt / NSTAGE) & 1);

        uint32_t astage = sbase + (uint32_t)st * STAGE_BYTES;
        uint32_t bstage = astage + A_WORDS * 4;

        #pragma unroll
        for (int ks = 0; ks < 4; ks++) {               // 4 x k16 per 64-chunk
            uint32_t af[4][4], bf[2][4];
            #pragma unroll
            for (int mt = 0; mt < 4; mt++)
                ldsm4(af[mt], astage + a_lm + mt * (16 * SROW_B) + ks * 32);
            #pragma unroll
            for (int p = 0; p < 2; p++)
                ldsm4(bf[p], bstage + b_lm + p * (16 * SROW_B) + ks * 32);
            #pragma unroll
            for (int mt = 0; mt < 4; mt++)
                #pragma unroll
                for (int nt = 0; nt < 4; nt++)
                    mma_f16(acc[mt][nt], af[mt], &bf[nt >> 1][(nt & 1) * 2]);
        }

        // stage consumed: MMAs above required ldsm completion, so smem reads
        // are architecturally done before this arrive issues (in-order issue)
        if (lane == 0) mbar_arrive(mb_emp + st * 8);
    }

    // ---- epilogue: + bias, fp32 out ----
    #pragma unroll
    for (int mt = 0; mt < 4; mt++) {
        int m0 = m_base + m_off + mt * 16 + g;
        #pragma unroll
        for (int nt = 0; nt < 4; nt++) {
            int n0 = n_off + nt * 8 + 2 * c;
            float b0v = bias_s[n0], b1v = bias_s[n0 + 1];
            float2 v;
            v.x = acc[mt][nt][0] + b0v;
            v.y = acc[mt][nt][1] + b1v;
            *(float2*)&out[(size_t)m0 * NDIM + n_base + n0] = v;
            v.x = acc[mt][nt][2] + b0v;
            v.y = acc[mt][nt][3] + b1v;
            *(float2*)&out[(size_t)(m0 + 8) * NDIM + n_base + n0] = v;
        }
    }
}

// ============================================================
// launch
// ============================================================
extern "C" void kernel_launch(void* const* d_in, const int* in_sizes, int n_in,
                              void* d_out, int out_size)
{
    const float* x        = (const float*)d_in[0];
    const float* codebook = (const float*)d_in[1];
    const int*   indices  = (const int*)  d_in[2];
    const int*   srows    = (const int*)  d_in[3];
    const int*   scols    = (const int*)  d_in[4];
    const float* sdeltas  = (const float*)d_in[5];
    const float* U        = (const float*)d_in[6];
    const float* s        = (const float*)d_in[7];
    const float* Vt       = (const float*)d_in[8];
    const float* bias     = (const float*)d_in[9];
    float* out = (float*)d_out;

    cudaFuncSetAttribute(gemm_kernel,
                         cudaFuncAttributeMaxDynamicSharedMemorySize, SMEM_TOTAL);
    cudaFuncSetAttribute(dequant_kernel,
                         cudaFuncAttributeMaxDynamicSharedMemorySize, DQ_SMEM_B);

    dequant_kernel<<<dim3(KDIM / 64, NDIM / 64), 256, DQ_SMEM_B>>>(
        codebook, indices, U, s, Vt);

    cvt_x_kernel<<<(int)(((size_t)MDIM * KDIM) / (256 * 8)), 256>>>(x);

    int nnz = in_sizes[3];
    scatter_kernel<<<(nnz + 255) / 256, 256>>>(srows, scols, sdeltas, nnz);

    gemm_kernel<<<dim3(NDIM / NT, MDIM / MT), 256, SMEM_TOTAL>>>(bias, out);
}

// round 16
// speedup vs baseline: 1.0312x; 1.0312x over previous
#include <cuda_runtime.h>
#include <cuda_fp16.h>
#include <cstdint>

// ---------------- problem constants ----------------
#define MDIM 8192
#define NDIM 4096
#define KDIM 4096

// ---------------- GEMM tiling (round-10 proven optimum) ----------------
// CTA tile 128x128, 8 warps (2m x 4n), warp tile 64x32, 2 CTAs per SM.
// KC=64, 3-stage mbarrier async pipeline (no mainloop __syncthreads).
#define MT 128
#define NT 128
#define KC 64                        // halfs per K-chunk = 128 bytes
#define KITERS (KDIM / KC)           // 64
#define NSTAGE 3
#define SROW_B 144                   // smem row stride bytes: 128 data + 16 pad
#define A_WORDS (MT * 36)            // 4608 words
#define B_WORDS (NT * 36)            // 4608 words
#define STAGE_WORDS (A_WORDS + B_WORDS)          // 9216 words = 36864 B
#define STAGE_BYTES (STAGE_WORDS * 4)
#define SMEM_WORDS (NSTAGE * STAGE_WORDS)        // 27648 words
#define SMEM_TOTAL (SMEM_WORDS * 4 + 1024)       // 111616 B (x2 CTAs = 223 KB)

// prep grid: 4096 dequant tiles + 16384 cvt blocks, interleaved 1:4
#define PREP_BLOCKS 20480

// ---------------- device scratch (static: no allocation) ----------------
__device__ __half g_Wh[(size_t)NDIM * KDIM];     // 32 MB fp16 W (dequant target)
__device__ __half g_xh[(size_t)MDIM * KDIM];     // 64 MB fp16 x

// ---------------- helpers ----------------
__device__ __forceinline__ uint32_t smem_u32(const void* p) {
    uint32_t a;
    asm("{ .reg .u64 t; cvta.to.shared.u64 t, %1; cvt.u32.u64 %0, t; }" : "=r"(a) : "l"(p));
    return a;
}
__device__ __forceinline__ void cp16(uint32_t dst, const void* src) {
    asm volatile("cp.async.cg.shared.global [%0], [%1], 16;" :: "r"(dst), "l"(src));
}
__device__ __forceinline__ void mbar_init(uint32_t a, uint32_t cnt) {
    asm volatile("mbarrier.init.shared.b64 [%0], %1;" :: "r"(a), "r"(cnt) : "memory");
}
__device__ __forceinline__ void mbar_arrive(uint32_t a) {
    asm volatile("mbarrier.arrive.shared.b64 _, [%0];" :: "r"(a) : "memory");
}
__device__ __forceinline__ void cp_arrive_noinc(uint32_t a) {
    asm volatile("cp.async.mbarrier.arrive.noinc.shared.b64 [%0];" :: "r"(a) : "memory");
}
__device__ __forceinline__ void mbar_wait(uint32_t a, uint32_t parity) {
    uint32_t done;
    asm volatile("{\n\t.reg .pred p;\n\t"
                 "mbarrier.try_wait.parity.acquire.cta.shared::cta.b64 p, [%1], %2;\n\t"
                 "selp.b32 %0, 1, 0, p;\n\t}"
                 : "=r"(done) : "r"(a), "r"(parity) : "memory");
    if (!done) {
        asm volatile("{\n\t.reg .pred P1;\n\t"
                     "WLOOP_%=:\n\t"
                     "mbarrier.try_wait.parity.acquire.cta.shared::cta.b64 P1, [%0], %1, 0x989680;\n\t"
                     "@P1 bra.uni WDONE_%=;\n\t"
                     "bra.uni WLOOP_%=;\n\t"
                     "WDONE_%=:\n\t}"
                     :: "r"(a), "r"(parity) : "memory");
    }
}
__device__ __forceinline__ void ldsm4(uint32_t* r, uint32_t addr) {
    asm volatile("ldmatrix.sync.aligned.m8n8.x4.shared.b16 {%0,%1,%2,%3}, [%4];"
        : "=r"(r[0]), "=r"(r[1]), "=r"(r[2]), "=r"(r[3]) : "r"(addr));
}
// mma.sync m16n8k16 fp16 -> fp32 accum
__device__ __forceinline__ void mma_f16(float* d, const uint32_t* a, const uint32_t* b) {
    asm volatile(
        "mma.sync.aligned.m16n8k16.row.col.f32.f16.f16.f32 "
        "{%0,%1,%2,%3}, {%4,%5,%6,%7}, {%8,%9}, {%0,%1,%2,%3};"
        : "+f"(d[0]), "+f"(d[1]), "+f"(d[2]), "+f"(d[3])
        : "r"(a[0]), "r"(a[1]), "r"(a[2]), "r"(a[3]), "r"(b[0]), "r"(b[1]));
}

// ============================================================
// Kernel 1 (interleaved prep):
//   bI % 5 == 0 -> dequant tile (4096 tiles of 64x64)
//   else        -> cvt_x block  (16384 blocks)
// Interleaving mixes L1-bound dequant with DRAM-bound cvt in
// every wave so the two bottlenecks overlap.
// ============================================================
__global__ __launch_bounds__(256)
void prep_kernel(const float* __restrict__ codebook,
                 const int*   __restrict__ indices,
                 const float* __restrict__ U,
                 const float* __restrict__ s,
                 const float* __restrict__ Vt,
                 const float* __restrict__ x)
{
    const int tid = threadIdx.x;
    const int bI  = blockIdx.x;

    if (bI % 5 != 0) {                // ---- cvt_x part (4 of every 5) ----
        int cvt_id = bI - bI / 5 - 1;
        size_t i = ((size_t)cvt_id * 256 + tid) * 8;
        float4 f0 = *(const float4*)&x[i];
        float4 f1 = *(const float4*)&x[i + 4];
        __half2 h0 = __floats2half2_rn(f0.x, f0.y);
        __half2 h1 = __floats2half2_rn(f0.z, f0.w);
        __half2 h2 = __floats2half2_rn(f1.x, f1.y);
        __half2 h3 = __floats2half2_rn(f1.z, f1.w);
        uint4 o;
        o.x = *reinterpret_cast<uint32_t*>(&h0);
        o.y = *reinterpret_cast<uint32_t*>(&h1);
        o.z = *reinterpret_cast<uint32_t*>(&h2);
        o.w = *reinterpret_cast<uint32_t*>(&h3);
        *(uint4*)&g_xh[i] = o;
        return;
    }

    // ---- dequant part: tile 64(out) x 64(in), 4x4 per thread ----
    __shared__ float UsT[32][64];    // transposed (U*s): [r][o]
    __shared__ float Vts[32][68];    // [r][i], padded
    __shared__ float cbs[256];

    const int dq = bI / 5;           // 0..4095
    const int o_base = (dq >> 6) * 64;
    const int i_base = (dq & 63) * 64;

    cbs[tid] = codebook[tid];
    #pragma unroll
    for (int q = 0; q < 8; q++) {
        int e = tid + 256 * q;
        int o = e >> 5, r = e & 31;
        UsT[r][o] = U[(size_t)(o_base + o) * 32 + r] * s[r];
        int r2 = e >> 6, i = e & 63;
        Vts[r2][i] = Vt[(size_t)r2 * KDIM + i_base + i];
    }
    __syncthreads();

    const int tx = tid & 15, ty = tid >> 4;
    float acc[4][4] = {};
    #pragma unroll
    for (int r = 0; r < 32; r++) {
        float4 a4 = *(const float4*)&UsT[r][ty * 4];
        float4 b4 = *(const float4*)&Vts[r][tx * 4];
        float av[4] = {a4.x, a4.y, a4.z, a4.w};
        float bv[4] = {b4.x, b4.y, b4.z, b4.w};
        #pragma unroll
        for (int io = 0; io < 4; io++)
            #pragma unroll
            for (int ii = 0; ii < 4; ii++)
                acc[io][ii] += av[io] * bv[ii];
    }

    #pragma unroll
    for (int io = 0; io < 4; io++) {
        int row = o_base + ty * 4 + io;
        size_t off = (size_t)row * KDIM + i_base + tx * 4;
        const int4 id4 = *(const int4*)&indices[off];
        __half2 h0 = __floats2half2_rn(cbs[id4.x] + acc[io][0],
                                       cbs[id4.y] + acc[io][1]);
        __half2 h1 = __floats2half2_rn(cbs[id4.z] + acc[io][2],
                                       cbs[id4.w] + acc[io][3]);
        uint2 o2;
        o2.x = *reinterpret_cast<uint32_t*>(&h0);
        o2.y = *reinterpret_cast<uint32_t*>(&h1);
        *(uint2*)&g_Wh[off] = o2;
    }
}

// ============================================================
// Kernel 2: sparse sidecar scatter (fp16 atomics into g_Wh)
// ============================================================
__global__ void scatter_kernel(const int* __restrict__ rows,
                               const int* __restrict__ cols,
                               const float* __restrict__ deltas, int n)
{
    int i = blockIdx.x * blockDim.x + threadIdx.x;
    if (i < n)
        atomicAdd(&g_Wh[(size_t)rows[i] * KDIM + cols[i]],
                  __float2half(deltas[i]));
}

// ============================================================
// Kernel 3: out = x @ W^T + bias   (round-10 GEMM, verbatim)
// CTA 128x128, 256 thr (8 warps, 2m x 4n), warp tile 64x32,
// 3-stage mbarrier async pipeline, 2 CTAs per SM.
// ============================================================
__global__ __launch_bounds__(256, 2)
void gemm_kernel(const float* __restrict__ bias, float* __restrict__ out)
{
    extern __shared__ uint32_t smem[];
    float* bias_s = (float*)(smem + SMEM_WORDS);

    const int tid  = threadIdx.x;
    const int wid  = tid >> 5, lane = tid & 31;
    const int g    = lane >> 2, c = lane & 3;          // quad group / id
    const int warp_m = wid & 1, warp_n = wid >> 1;
    const int m_off  = warp_m * 64, n_off = warp_n * 32;
    const int m_base = blockIdx.y * MT;
    const int n_base = blockIdx.x * NT;

    const uint32_t sbase   = smem_u32(smem);
    const uint32_t mb_full = sbase + SMEM_WORDS * 4 + 512;   // 3 x 8 B
    const uint32_t mb_emp  = mb_full + 24;                   // 3 x 8 B

    if (tid < NT) bias_s[tid] = bias[n_base + tid];
    if (tid == 0) {
        #pragma unroll
        for (int st = 0; st < NSTAGE; st++) {
            mbar_init(mb_full + st * 8, 256);   // one cp-arrive per thread
            mbar_init(mb_emp  + st * 8, 8);     // one arrive per warp
        }
    }
    __syncthreads();                            // barriers visible; only sync

    const __half* xrow = g_xh + (size_t)m_base * KDIM;
    const __half* wrow = g_Wh + (size_t)n_base * KDIM;

    // ldmatrix per-lane byte offsets (within a stage)
    const uint32_t a_lm = (uint32_t)(m_off + ((lane >> 3) & 1) * 8 + (lane & 7)) * SROW_B
                        + (lane >> 4) * 16;
    const uint32_t b_lm = (uint32_t)(n_off + (lane >> 4) * 8 + (lane & 7)) * SROW_B
                        + ((lane >> 3) & 1) * 16;

    // producer: wait stage-empty, fill via cp.async, arm full barrier
    auto produce = [&](int j) {
        int st = j % NSTAGE;
        mbar_wait(mb_emp + st * 8, ((j / NSTAGE) & 1) ^ 1);
        uint32_t a0 = sbase + (uint32_t)st * STAGE_BYTES;
        uint32_t b0 = a0 + A_WORDS * 4;
        const __half* as = xrow + (size_t)j * KC;
        const __half* bs = wrow + (size_t)j * KC;
        #pragma unroll
        for (int q = 0; q < 4; q++) {                  // A: 1024 segs / 256 thr
            int e = tid + 256 * q;
            int row = e >> 3, seg = e & 7;
            cp16(a0 + row * SROW_B + seg * 16, as + (size_t)row * KDIM + seg * 8);
        }
        #pragma unroll
        for (int q = 0; q < 4; q++) {                  // B: 1024 segs / 256 thr
            int e = tid + 256 * q;
            int row = e >> 3, seg = e & 7;
            cp16(b0 + row * SROW_B + seg * 16, bs + (size_t)row * KDIM + seg * 8);
        }
        cp_arrive_noinc(mb_full + st * 8);
    };

    produce(0);
    produce(1);

    float acc[4][4][4] = {};

    for (int kt = 0; kt < KITERS; kt++) {
        int nxt = kt + NSTAGE - 1;
        if (nxt < KITERS) produce(nxt);

        int st = kt % NSTAGE;
        mbar_wait(mb_full + st * 8, (kt / NSTAGE) & 1);

        uint32_t astage = sbase + (uint32_t)st * STAGE_BYTES;
        uint32_t bstage = astage + A_WORDS * 4;

        #pragma unroll
        for (int ks = 0; ks < 4; ks++) {               // 4 x k16 per 64-chunk
            uint32_t af[4][4], bf[2][4];
            #pragma unroll
            for (int mt = 0; mt < 4; mt++)
                ldsm4(af[mt], astage + a_lm + mt * (16 * SROW_B) + ks * 32);
            #pragma unroll
            for (int p = 0; p < 2; p++)
                ldsm4(bf[p], bstage + b_lm + p * (16 * SROW_B) + ks * 32);
            #pragma unroll
            for (int mt = 0; mt < 4; mt++)
                #pragma unroll
                for (int nt = 0; nt < 4; nt++)
                    mma_f16(acc[mt][nt], af[mt], &bf[nt >> 1][(nt & 1) * 2]);
        }

        // stage consumed: MMAs above required ldsm completion, so smem reads
        // are architecturally done before this arrive issues (in-order issue)
        if (lane == 0) mbar_arrive(mb_emp + st * 8);
    }

    // ---- epilogue: + bias, fp32 out ----
    #pragma unroll
    for (int mt = 0; mt < 4; mt++) {
        int m0 = m_base + m_off + mt * 16 + g;
        #pragma unroll
        for (int nt = 0; nt < 4; nt++) {
            int n0 = n_off + nt * 8 + 2 * c;
            float b0v = bias_s[n0], b1v = bias_s[n0 + 1];
            float2 v;
            v.x = acc[mt][nt][0] + b0v;
            v.y = acc[mt][nt][1] + b1v;
            *(float2*)&out[(size_t)m0 * NDIM + n_base + n0] = v;
            v.x = acc[mt][nt][2] + b0v;
            v.y = acc[mt][nt][3] + b1v;
            *(float2*)&out[(size_t)(m0 + 8) * NDIM + n_base + n0] = v;
        }
    }
}

// ============================================================
// launch
// ============================================================
extern "C" void kernel_launch(void* const* d_in, const int* in_sizes, int n_in,
                              void* d_out, int out_size)
{
    const float* x        = (const float*)d_in[0];
    const float* codebook = (const float*)d_in[1];
    const int*   indices  = (const int*)  d_in[2];
    const int*   srows    = (const int*)  d_in[3];
    const int*   scols    = (const int*)  d_in[4];
    const float* sdeltas  = (const float*)d_in[5];
    const float* U        = (const float*)d_in[6];
    const float* s        = (const float*)d_in[7];
    const float* Vt       = (const float*)d_in[8];
    const float* bias     = (const float*)d_in[9];
    float* out = (float*)d_out;

    cudaFuncSetAttribute(gemm_kernel,
                         cudaFuncAttributeMaxDynamicSharedMemorySize, SMEM_TOTAL);

    // interleaved: 4096 dequant tiles (bI%5==0) + 16384 cvt blocks
    prep_kernel<<<PREP_BLOCKS, 256>>>(codebook, indices, U, s, Vt, x);

    int nnz = in_sizes[3];
    scatter_kernel<<<(nnz + 255) / 256, 256>>>(srows, scols, sdeltas, nnz);

    gemm_kernel<<<dim3(NDIM / NT, MDIM / MT), 256, SMEM_TOTAL>>>(bias, out);
}